// round 1
// baseline (speedup 1.0000x reference)
#include <cuda_runtime.h>
#include <cstdint>
#include <cstddef>

// Problem constants (fixed for IcoGenericUpConv_8641474199780)
#define BB    16
#define CIN   256
#define COUT  128
#define NLOW  10242
#define NUP   40962
#define KK    7
#define FF    (KK * COUT)      // 896
#define VK    (NLOW * KK)      // 71694

// Scratch: accumulator in [u][b][co] layout (contiguous 2048 floats per u)
// plus per-up-vertex counts. Static __device__ arrays (allocation-free rule).
__device__ float g_accum[(size_t)NUP * BB * COUT];   // 335.5 MB
__device__ int   g_cnt[NUP];

// ---------------------------------------------------------------------------
// Kernel 1: zero the accumulator and counts.
// ---------------------------------------------------------------------------
__global__ void k_zero() {
  const size_t n4 = ((size_t)NUP * BB * COUT) / 4;
  const float4 z = make_float4(0.f, 0.f, 0.f, 0.f);
  const size_t stride = (size_t)gridDim.x * blockDim.x;
  for (size_t i = (size_t)blockIdx.x * blockDim.x + threadIdx.x; i < n4; i += stride)
    reinterpret_cast<float4*>(g_accum)[i] = z;
  for (size_t i = (size_t)blockIdx.x * blockDim.x + threadIdx.x; i < (size_t)NUP; i += stride)
    g_cnt[i] = 0;
}

// ---------------------------------------------------------------------------
// Kernel 2: segment counts.
// ---------------------------------------------------------------------------
__global__ void k_count(const int* __restrict__ neigh) {
  const int i = blockIdx.x * blockDim.x + threadIdx.x;
  if (i < VK) atomicAdd(&g_cnt[neigh[i]], 1);
}

// ---------------------------------------------------------------------------
// FFMA2 helpers: packed f32x2 FMA (rt 2, but 2 FMA/inst -> 128 FMA/cyc/SM,
// double the FFMA-3reg rate on sm_103a).
// ---------------------------------------------------------------------------
__device__ __forceinline__ unsigned long long ffma2(unsigned long long a,
                                                    unsigned long long b,
                                                    unsigned long long c) {
  unsigned long long d;
  asm("fma.rn.f32x2 %0, %1, %2, %3;" : "=l"(d) : "l"(a), "l"(b), "l"(c));
  return d;
}
__device__ __forceinline__ unsigned long long dup2(float v) {
  unsigned long long d;
  unsigned int r = __float_as_uint(v);
  asm("mov.b64 %0, {%1, %1};" : "=l"(d) : "r"(r));
  return d;
}

// ---------------------------------------------------------------------------
// Kernel 3: fused GEMM + atomic scatter.
// Block = 8 low-vertices. M-tile = 128 rows (m = b*8 + vl, so 8 consecutive
// v per b -> 32B-sector-coalesced A loads). Full A panel (128 x 256 fp32,
// 128 KB) is loaded into dynamic smem ONCE, then all 7 k-blocks of N=128
// are computed from it (x read once from HBM; W served from L2).
// 256 threads (16x16), 8x8 fp32 micro-tile each, via packed f32x2 FMA.
// Epilogue: add bias, RED.ADD.F32 into g_accum[u][b][co].
// ---------------------------------------------------------------------------
__global__ void __launch_bounds__(256, 1) k_gemm_scatter(
    const float* __restrict__ x,      // [B, CIN, NLOW]
    const float* __restrict__ w,      // [CIN, FF]
    const float* __restrict__ bias,   // [FF]
    const int*   __restrict__ neigh)  // [VK]
{
  extern __shared__ float smem[];
  float* As = smem;               // [256][128]  (c-major, m contiguous)
  float* Bs = smem + 256 * 128;   // [8][128]

  const int tid = threadIdx.x;
  const int ty  = tid >> 4;       // 0..15  == batch index b
  const int tx  = tid & 15;       // column group (cols tx*8 .. tx*8+7)
  const int v0  = blockIdx.x * 8;

  // Load A panel: As[c][m], m = b*8 + vl, value = x[b][c][v0+vl]
  for (int idx = tid; idx < 256 * 128; idx += 256) {
    const int c  = idx >> 7;
    const int m  = idx & 127;
    const int b  = m >> 3;
    const int vl = m & 7;
    const int v  = v0 + vl;
    As[idx] = (v < NLOW) ? x[((size_t)b * CIN + c) * NLOW + v] : 0.0f;
  }
  __syncthreads();

  for (int k = 0; k < KK; ++k) {
    unsigned long long acc[8][4];   // 8 rows x 4 col-pairs (= 8 cols)
#pragma unroll
    for (int i = 0; i < 8; ++i)
#pragma unroll
      for (int j = 0; j < 4; ++j) acc[i][j] = 0ull;

    for (int c0 = 0; c0 < CIN; c0 += 8) {
      // Load B tile: Bs[cl][n] = W[c0+cl][k*128 + n]  (float4, coalesced)
      {
        const int cl = tid >> 5;
        const int n  = (tid & 31) * 4;
        *reinterpret_cast<float4*>(&Bs[cl * 128 + n]) =
            *reinterpret_cast<const float4*>(&w[(size_t)(c0 + cl) * FF + k * COUT + n]);
      }
      __syncthreads();

#pragma unroll
      for (int cl = 0; cl < 8; ++cl) {
        const float4 a0 = *reinterpret_cast<const float4*>(&As[(c0 + cl) * 128 + ty * 8]);
        const float4 a1 = *reinterpret_cast<const float4*>(&As[(c0 + cl) * 128 + ty * 8 + 4]);
        const ulonglong2 b0 = *reinterpret_cast<const ulonglong2*>(&Bs[cl * 128 + tx * 8]);
        const ulonglong2 b1 = *reinterpret_cast<const ulonglong2*>(&Bs[cl * 128 + tx * 8 + 4]);
        const unsigned long long ad[8] = {dup2(a0.x), dup2(a0.y), dup2(a0.z), dup2(a0.w),
                                          dup2(a1.x), dup2(a1.y), dup2(a1.z), dup2(a1.w)};
        const unsigned long long bp[4] = {b0.x, b0.y, b1.x, b1.y};
#pragma unroll
        for (int i = 0; i < 8; ++i)
#pragma unroll
          for (int j = 0; j < 4; ++j)
            acc[i][j] = ffma2(ad[i], bp[j], acc[i][j]);
      }
      __syncthreads();
    }

    // Epilogue: add bias, scatter via fire-and-forget float atomics.
    const float4 bias0 = *reinterpret_cast<const float4*>(&bias[k * COUT + tx * 8]);
    const float4 bias1 = *reinterpret_cast<const float4*>(&bias[k * COUT + tx * 8 + 4]);
    const float bj[8] = {bias0.x, bias0.y, bias0.z, bias0.w,
                         bias1.x, bias1.y, bias1.z, bias1.w};
#pragma unroll
    for (int i = 0; i < 8; ++i) {
      const int v = v0 + i;
      if (v < NLOW) {
        const int u = neigh[v * KK + k];
        float* dst = &g_accum[((size_t)u * BB + ty) * COUT + tx * 8];
#pragma unroll
        for (int j = 0; j < 4; ++j) {
          union { unsigned long long q; float2 f; } cv;
          cv.q = acc[i][j];
          atomicAdd(dst + 2 * j,     cv.f.x + bj[2 * j]);
          atomicAdd(dst + 2 * j + 1, cv.f.y + bj[2 * j + 1]);
        }
      }
    }
  }
}

// ---------------------------------------------------------------------------
// Kernel 4: divide by counts and transpose [u][bc] -> out[bc][u].
// 32x32 tile through padded smem; coalesced on both sides.
// ---------------------------------------------------------------------------
__global__ void k_finalize(float* __restrict__ out) {
  __shared__ float t[32][33];
  __shared__ float inv[32];
  const int u0 = blockIdx.x * 32;
  const int c0 = blockIdx.y * 32;
  const int lx = threadIdx.x;   // 0..31
  const int ly = threadIdx.y;   // 0..7

  if (ly == 0) {
    const int u = u0 + lx;
    inv[lx] = (u < NUP) ? (1.0f / (float)g_cnt[u]) : 0.0f;
  }
  __syncthreads();

#pragma unroll
  for (int r = ly; r < 32; r += 8) {
    const int u = u0 + r;
    t[r][lx] = (u < NUP)
                 ? g_accum[(size_t)u * (BB * COUT) + c0 + lx] * inv[r]
                 : 0.0f;
  }
  __syncthreads();

#pragma unroll
  for (int r = ly; r < 32; r += 8) {
    const int bc = c0 + r;
    const int u  = u0 + lx;
    if (u < NUP) out[(size_t)bc * NUP + u] = t[lx][r];
  }
}

// ---------------------------------------------------------------------------
// Launch. Inputs (metadata order): x f32, weight f32, bias f32,
// neigh_flat i32, n_up i32 (unused; dims are compile-time constants).
// ---------------------------------------------------------------------------
extern "C" void kernel_launch(void* const* d_in, const int* in_sizes, int n_in,
                              void* d_out, int out_size) {
  const float* x     = (const float*)d_in[0];
  const float* w     = (const float*)d_in[1];
  const float* bias  = (const float*)d_in[2];
  const int*   neigh = (const int*)d_in[3];
  float* out = (float*)d_out;

  k_zero<<<2048, 256>>>();
  k_count<<<(VK + 255) / 256, 256>>>(neigh);

  const int smem_bytes = (256 * 128 + 8 * 128) * (int)sizeof(float);  // 132 KB
  cudaFuncSetAttribute(k_gemm_scatter,
                       cudaFuncAttributeMaxDynamicSharedMemorySize, smem_bytes);
  k_gemm_scatter<<<(NLOW + 7) / 8, 256, smem_bytes>>>(x, w, bias, neigh);

  dim3 fgrid((NUP + 31) / 32, (BB * COUT) / 32);
  k_finalize<<<fgrid, dim3(32, 8)>>>(out);
}

// round 9
// speedup vs baseline: 3.3116x; 3.3116x over previous
#include <cuda_runtime.h>
#include <cuda_bf16.h>
#include <cstdint>
#include <cstddef>

// Problem constants (fixed for IcoGenericUpConv_8641474199780)
#define BB    16
#define CIN   256
#define COUT  128
#define NLOW  10242
#define NUP   40962
#define KK    7
#define FF    (KK * COUT)          // 896
#define VK    (NLOW * KK)          // 71694
#define MTOT  (NLOW * BB)          // 163872 rows, m = v*16 + b
#define MTILES ((MTOT + 127) / 128) // 1281

// ---------------------------------------------------------------------------
// Scratch (__device__ globals; zero-initialized at module load)
// ---------------------------------------------------------------------------
__device__ float        g_accum[(size_t)NUP * BB * COUT];        // 335.5 MB
__device__ int          g_cnt[NUP];
__device__ __nv_bfloat16 g_Ah[(size_t)MTILES * 128 * CIN];       // 84 MB
__device__ __nv_bfloat16 g_Al[(size_t)MTILES * 128 * CIN];       // 84 MB
__device__ __nv_bfloat16 g_Bh[(size_t)FF * CIN];                 // 458 KB
__device__ __nv_bfloat16 g_Bl[(size_t)FF * CIN];

// ---------------------------------------------------------------------------
// Helpers (baseline PTX only — no 'a'-gated features; harness targets sm_103)
// ---------------------------------------------------------------------------
__device__ __forceinline__ uint32_t smem_u32(const void* p) {
  uint32_t a;
  asm("{ .reg .u64 t; cvta.to.shared.u64 t, %1; cvt.u32.u64 %0, t; }"
      : "=r"(a) : "l"(p));
  return a;
}

// cp.async 16B, L1-bypass (sm_80 baseline)
__device__ __forceinline__ void cpa16(uint32_t dst, const void* src) {
  asm volatile("cp.async.cg.shared.global [%0], [%1], 16;"
               :: "r"(dst), "l"(src) : "memory");
}
__device__ __forceinline__ void cpa_commit_wait0() {
  asm volatile("cp.async.commit_group;" ::: "memory");
  asm volatile("cp.async.wait_group 0;" ::: "memory");
}

// ldmatrix (sm_75 baseline)
__device__ __forceinline__ void ldsm_x4(uint32_t* r, uint32_t addr) {
  asm volatile("ldmatrix.sync.aligned.m8n8.x4.shared.b16 {%0,%1,%2,%3}, [%4];"
               : "=r"(r[0]), "=r"(r[1]), "=r"(r[2]), "=r"(r[3]) : "r"(addr));
}
__device__ __forceinline__ void ldsm_x2(uint32_t& r0, uint32_t& r1, uint32_t addr) {
  asm volatile("ldmatrix.sync.aligned.m8n8.x2.shared.b16 {%0,%1}, [%2];"
               : "=r"(r0), "=r"(r1) : "r"(addr));
}

// bf16 HMMA m16n8k16 (sm_80 baseline): D(16x8 f32) += A(16x16) @ B(16x8)
__device__ __forceinline__ void mma16816(float* d, const uint32_t* a,
                                         uint32_t b0, uint32_t b1) {
  asm volatile(
      "mma.sync.aligned.m16n8k16.row.col.f32.bf16.bf16.f32 "
      "{%0,%1,%2,%3}, {%4,%5,%6,%7}, {%8,%9}, {%0,%1,%2,%3};"
      : "+f"(d[0]), "+f"(d[1]), "+f"(d[2]), "+f"(d[3])
      : "r"(a[0]), "r"(a[1]), "r"(a[2]), "r"(a[3]), "r"(b0), "r"(b1));
}

// vector float reduction (compiled clean on sm_103 in round-8 log)
__device__ __forceinline__ void red2(float* p, float x, float y) {
  asm volatile("red.global.add.v2.f32 [%0], {%1, %2};"
               :: "l"(p), "f"(x), "f"(y) : "memory");
}

// ---------------------------------------------------------------------------
// SMEM layout for the MMA kernel (dynamic, 192 KB)
// A tiles: 128 rows x 256 bf16, 512 B/row, 16B chunks XOR-swizzled by (row&7).
// B tiles: 128 rows x 128 bf16, 256 B/row, same swizzle.
// ---------------------------------------------------------------------------
#define OFF_AH   0
#define OFF_AL   65536
#define OFF_BH   131072
#define OFF_BL   163840
#define SMEM_TOT 196608

// ---------------------------------------------------------------------------
// Kernel: zero accumulator + counts
// ---------------------------------------------------------------------------
__global__ void k_zero() {
  const size_t n4 = ((size_t)NUP * BB * COUT) / 4;
  const float4 z = make_float4(0.f, 0.f, 0.f, 0.f);
  const size_t stride = (size_t)gridDim.x * blockDim.x;
  for (size_t i = (size_t)blockIdx.x * blockDim.x + threadIdx.x; i < n4; i += stride)
    reinterpret_cast<float4*>(g_accum)[i] = z;
  for (size_t i = (size_t)blockIdx.x * blockDim.x + threadIdx.x; i < (size_t)NUP; i += stride)
    g_cnt[i] = 0;
}

__global__ void k_count(const int* __restrict__ neigh) {
  const int i = blockIdx.x * blockDim.x + threadIdx.x;
  if (i < VK) atomicAdd(&g_cnt[neigh[i]], 1);
}

// ---------------------------------------------------------------------------
// Prep: x [B][CIN][NLOW] f32 -> A_hi/A_lo [m = v*16+b][c] bf16 (hi/lo split)
// ---------------------------------------------------------------------------
__global__ void __launch_bounds__(256) prep_x(const float* __restrict__ x) {
  __shared__ float s[32][65];
  const int v0 = blockIdx.x * 64, c0 = blockIdx.y * 32, b = blockIdx.z;
  const int tid = threadIdx.x;
  for (int i = tid; i < 32 * 64; i += 256) {
    const int cl = i >> 6, vl = i & 63, v = v0 + vl;
    s[cl][vl] = (v < NLOW) ? x[((size_t)b * CIN + c0 + cl) * NLOW + v] : 0.f;
  }
  __syncthreads();
  for (int i = tid; i < 64 * 32; i += 256) {
    const int vl = i >> 5, cl = i & 31, v = v0 + vl;
    if (v < NLOW) {
      const float val = s[cl][vl];
      const __nv_bfloat16 hi = __float2bfloat16(val);
      const __nv_bfloat16 lo = __float2bfloat16(val - __bfloat162float(hi));
      const size_t m = (size_t)v * BB + b;
      g_Ah[m * CIN + c0 + cl] = hi;
      g_Al[m * CIN + c0 + cl] = lo;
    }
  }
}

// ---------------------------------------------------------------------------
// Prep: W [CIN][FF] f32 -> B_hi/B_lo [f][c] bf16 (transposed, hi/lo split)
// ---------------------------------------------------------------------------
__global__ void __launch_bounds__(256) prep_w(const float* __restrict__ w) {
  __shared__ float s[32][33];
  const int f0 = blockIdx.x * 32, c0 = blockIdx.y * 32;
  const int lane = threadIdx.x & 31, wr = threadIdx.x >> 5;
  for (int r = wr; r < 32; r += 8)
    s[r][lane] = w[(size_t)(c0 + r) * FF + f0 + lane];
  __syncthreads();
  for (int r = wr; r < 32; r += 8) {
    const float val = s[lane][r];
    const __nv_bfloat16 hi = __float2bfloat16(val);
    const __nv_bfloat16 lo = __float2bfloat16(val - __bfloat162float(hi));
    g_Bh[(size_t)(f0 + r) * CIN + c0 + lane] = hi;
    g_Bl[(size_t)(f0 + r) * CIN + c0 + lane] = lo;
  }
}

__global__ void k_nop() {}

// ---------------------------------------------------------------------------
// Main kernel: warp-level bf16 mma.sync (hi/lo compensated) + atomic scatter.
// CTA = one 128-row m-tile (8 v x 16 b), 256 threads = 8 warps (4m x 2n).
// A (hi+lo) resident in smem; per k (N-block of 128), two B k-chunks are
// streamed and a 128x128 fp32 C tile accumulates in registers. Epilogue adds
// bias and red.v2's into g_accum[u][b][co].
// ---------------------------------------------------------------------------
__global__ void __launch_bounds__(256, 1) k_mma(const float* __restrict__ bias,
                                                const int* __restrict__ neigh) {
  extern __shared__ __align__(128) char smem[];
  const uint32_t base = smem_u32(smem);
  const int tid  = threadIdx.x;
  const int wid  = tid >> 5;
  const int lane = tid & 31;
  const int wm   = wid & 3;        // warp m-row (0..3) -> 32 rows
  const int wn   = wid >> 2;       // warp n-col (0..1) -> 64 cols
  const int m0w  = wm * 32;
  const int n0w  = wn * 64;
  const int m0   = blockIdx.x * 128;

  // ---- Load A tile (hi + lo) resident: 128 rows x 32 16B-chunks each ----
  for (int i = tid; i < 4096; i += 256) {
    const int r = i >> 5, cc = i & 31;
    const uint32_t dst = (uint32_t)(r * 512 + ((cc ^ (r & 7)) << 4));
    const size_t src = ((size_t)(m0 + r)) * CIN + cc * 8;
    cpa16(base + OFF_AH + dst, &g_Ah[src]);
    cpa16(base + OFF_AL + dst, &g_Al[src]);
  }
  cpa_commit_wait0();
  __syncthreads();

  // Per-lane ldmatrix address components
  const int asub = lane >> 3;            // 0..3
  const int arow_lo = (asub & 1) * 8 + (lane & 7);   // row offset within 16
  const int achunk_add = asub >> 1;                  // +0 or +1 chunk
  const int bsub = (lane >> 3) & 1;      // 0/1 (lanes 16-31 mirror 0-15)
  const int brow = lane & 7;

  for (int k = 0; k < KK; ++k) {
    float d[2][8][4];
#pragma unroll
    for (int mt = 0; mt < 2; ++mt)
#pragma unroll
      for (int nt = 0; nt < 8; ++nt)
#pragma unroll
        for (int q = 0; q < 4; ++q) d[mt][nt][q] = 0.f;

    for (int ch = 0; ch < 2; ++ch) {
      __syncthreads();   // all warps done with previous B chunk
      // ---- Load B chunk (hi + lo): rows f = k*128 + n, k-cols ch*128.. ----
      for (int i = tid; i < 2048; i += 256) {
        const int n = i >> 4, cc = i & 15;
        const uint32_t dst = (uint32_t)(n * 256 + ((cc ^ (n & 7)) << 4));
        const size_t src = ((size_t)(k * COUT + n)) * CIN + ch * 128 + cc * 8;
        cpa16(base + OFF_BH + dst, &g_Bh[src]);
        cpa16(base + OFF_BL + dst, &g_Bl[src]);
      }
      cpa_commit_wait0();
      __syncthreads();

#pragma unroll
      for (int ks = 0; ks < 8; ++ks) {
        // A fragments (hi+lo) for both 16-row m-tiles
        const int cA = ch * 16 + ks * 2 + achunk_add;
        uint32_t ah[2][4], al[2][4];
#pragma unroll
        for (int mt = 0; mt < 2; ++mt) {
          const int row = m0w + mt * 16 + arow_lo;
          const uint32_t aoff =
              (uint32_t)(row * 512 + ((cA ^ (row & 7)) << 4));
          ldsm_x4(ah[mt], base + OFF_AH + aoff);
          ldsm_x4(al[mt], base + OFF_AL + aoff);
        }
        // B fragments per 8-col n-tile; rows n0w+nt*8+brow (brow<8 so
        // (row&7)==brow regardless of nt -> swizzle term constant)
        const int cB = ks * 2 + bsub;
        const uint32_t boff0 =
            (uint32_t)((n0w + brow) * 256 + ((cB ^ brow) << 4));
#pragma unroll
        for (int nt = 0; nt < 8; ++nt) {
          uint32_t bh0, bh1, bl0, bl1;
          const uint32_t ba = boff0 + (uint32_t)(nt * 2048);
          ldsm_x2(bh0, bh1, base + OFF_BH + ba);
          ldsm_x2(bl0, bl1, base + OFF_BL + ba);
#pragma unroll
          for (int mt = 0; mt < 2; ++mt) {
            mma16816(d[mt][nt], ah[mt], bh0, bh1);   // hi*hi
            mma16816(d[mt][nt], ah[mt], bl0, bl1);   // hi*lo
            mma16816(d[mt][nt], al[mt], bh0, bh1);   // lo*hi
          }
        }
      }
    }

    // ---- Epilogue for this k: bias + red.v2 scatter into g_accum ----
    const int l4 = lane >> 2;            // 0..7
    const int l2 = (lane & 3) * 2;       // 0,2,4,6
#pragma unroll
    for (int mt = 0; mt < 2; ++mt) {
#pragma unroll
      for (int h = 0; h < 2; ++h) {      // h=0 -> c0,c1 ; h=1 -> c2,c3 (+8 rows)
        const int m = m0 + m0w + mt * 16 + h * 8 + l4;
        if (m < MTOT) {
          const int v = m >> 4;
          const int b = m & 15;
          const int u = neigh[v * KK + k];
          float* dp = g_accum + ((size_t)u * BB + b) * COUT;
#pragma unroll
          for (int nt = 0; nt < 8; ++nt) {
            const int col = n0w + nt * 8 + l2;
            const float2 bb =
                *reinterpret_cast<const float2*>(&bias[k * COUT + col]);
            red2(dp + col, d[mt][nt][h * 2 + 0] + bb.x,
                           d[mt][nt][h * 2 + 1] + bb.y);
          }
        }
      }
    }
  }
}

// ---------------------------------------------------------------------------
// Finalize: divide by counts and transpose [u][bc] -> out[bc][u].
// Tile: 32 u x 128 bc, float4 reads, padded smem transpose.
// ---------------------------------------------------------------------------
__global__ void __launch_bounds__(256) k_finalize(float* __restrict__ out) {
  __shared__ float t[32][129];
  __shared__ float inv[32];
  const int u0 = blockIdx.x * 32, c0 = blockIdx.y * 128;
  const int tid = threadIdx.x, lane = tid & 31, wr = tid >> 5;

  if (tid < 32) inv[tid] = (u0 + tid < NUP) ? 1.0f / (float)g_cnt[u0 + tid] : 0.f;

  for (int i = tid; i < 1024; i += 256) {   // 32 u x 32 float4
    const int ur = i >> 5, c4 = i & 31;
    const int u = u0 + ur;
    float4 v = make_float4(0.f, 0.f, 0.f, 0.f);
    if (u < NUP)
      v = *reinterpret_cast<const float4*>(&g_accum[(size_t)u * (BB * COUT) + c0 + c4 * 4]);
    t[ur][c4 * 4 + 0] = v.x;
    t[ur][c4 * 4 + 1] = v.y;
    t[ur][c4 * 4 + 2] = v.z;
    t[ur][c4 * 4 + 3] = v.w;
  }
  __syncthreads();

  const int u = u0 + lane;
  if (u < NUP) {
    const float iv = inv[lane];
    for (int r = wr; r < 128; r += 8)
      out[(size_t)(c0 + r) * NUP + u] = t[lane][r] * iv;
  }
}

// ---------------------------------------------------------------------------
// Launch. Inputs: x f32, weight f32, bias f32, neigh_flat i32, n_up i32.
// ---------------------------------------------------------------------------
extern "C" void kernel_launch(void* const* d_in, const int* in_sizes, int n_in,
                              void* d_out, int out_size) {
  const float* x     = (const float*)d_in[0];
  const float* w     = (const float*)d_in[1];
  const float* bias  = (const float*)d_in[2];
  const int*   neigh = (const int*)d_in[3];
  float* out = (float*)d_out;

  k_zero<<<2048, 256>>>();
  k_count<<<(VK + 255) / 256, 256>>>(neigh);
  prep_x<<<dim3((NLOW + 63) / 64, CIN / 32, BB), 256>>>(x);
  prep_w<<<dim3(FF / 32, CIN / 32), 256>>>(w);
  k_nop<<<1, 32>>>();   // spacer so ncu -s 5 profiles k_mma (launch #6)

  cudaFuncSetAttribute(k_mma, cudaFuncAttributeMaxDynamicSharedMemorySize, SMEM_TOT);
  k_mma<<<MTILES, 256, SMEM_TOT>>>(bias, neigh);

  k_finalize<<<dim3((NUP + 31) / 32, (BB * COUT) / 128), 256>>>(out);
}

// round 11
// speedup vs baseline: 3.5063x; 1.0588x over previous
#include <cuda_runtime.h>
#include <cuda_bf16.h>
#include <cstdint>
#include <cstddef>

// Problem constants (fixed for IcoGenericUpConv_8641474199780)
#define BB    16
#define CIN   256
#define COUT  128
#define NLOW  10242
#define NUP   40962
#define KK    7
#define FF    (KK * COUT)          // 896
#define VK    (NLOW * KK)          // 71694
#define MTOT  (NLOW * BB)          // 163872 rows, m = v*16 + b
#define MTILES ((MTOT + 127) / 128) // 1281
#define NSUB  (KK * 4)             // 28 B sub-chunks (64 k-cols each)

// ---------------------------------------------------------------------------
// Scratch (__device__ globals)
// ---------------------------------------------------------------------------
__device__ float        g_accum[(size_t)NUP * BB * COUT];        // 335.5 MB
__device__ int          g_cnt[NUP];
__device__ __nv_bfloat16 g_Ah[(size_t)MTILES * 128 * CIN];       // 84 MB
__device__ __nv_bfloat16 g_Al[(size_t)MTILES * 128 * CIN];       // 84 MB
__device__ __nv_bfloat16 g_Bh[(size_t)FF * CIN];                 // 458 KB
__device__ __nv_bfloat16 g_Bl[(size_t)FF * CIN];

// ---------------------------------------------------------------------------
// Helpers (baseline PTX only — harness ptxas targets plain sm_103)
// ---------------------------------------------------------------------------
__device__ __forceinline__ uint32_t smem_u32(const void* p) {
  uint32_t a;
  asm("{ .reg .u64 t; cvta.to.shared.u64 t, %1; cvt.u32.u64 %0, t; }"
      : "=r"(a) : "l"(p));
  return a;
}

__device__ __forceinline__ void cpa16(uint32_t dst, const void* src) {
  asm volatile("cp.async.cg.shared.global [%0], [%1], 16;"
               :: "r"(dst), "l"(src) : "memory");
}
__device__ __forceinline__ void cpa_commit() {
  asm volatile("cp.async.commit_group;" ::: "memory");
}
__device__ __forceinline__ void cpa_wait1() {
  asm volatile("cp.async.wait_group 1;" ::: "memory");
}
__device__ __forceinline__ void cpa_wait0() {
  asm volatile("cp.async.wait_group 0;" ::: "memory");
}

__device__ __forceinline__ void ldsm_x4(uint32_t* r, uint32_t addr) {
  asm volatile("ldmatrix.sync.aligned.m8n8.x4.shared.b16 {%0,%1,%2,%3}, [%4];"
               : "=r"(r[0]), "=r"(r[1]), "=r"(r[2]), "=r"(r[3]) : "r"(addr));
}
__device__ __forceinline__ void ldsm_x2(uint32_t& r0, uint32_t& r1, uint32_t addr) {
  asm volatile("ldmatrix.sync.aligned.m8n8.x2.shared.b16 {%0,%1}, [%2];"
               : "=r"(r0), "=r"(r1) : "r"(addr));
}

// bf16 HMMA m16n8k16 (sm_80 baseline)
__device__ __forceinline__ void mma16816(float* d, const uint32_t* a,
                                         uint32_t b0, uint32_t b1) {
  asm volatile(
      "mma.sync.aligned.m16n8k16.row.col.f32.bf16.bf16.f32 "
      "{%0,%1,%2,%3}, {%4,%5,%6,%7}, {%8,%9}, {%0,%1,%2,%3};"
      : "+f"(d[0]), "+f"(d[1]), "+f"(d[2]), "+f"(d[3])
      : "r"(a[0]), "r"(a[1]), "r"(a[2]), "r"(a[3]), "r"(b0), "r"(b1));
}

__device__ __forceinline__ void red4g(float* p, float x, float y, float z, float w) {
  asm volatile("red.global.add.v4.f32 [%0], {%1, %2, %3, %4};"
               :: "l"(p), "f"(x), "f"(y), "f"(z), "f"(w) : "memory");
}

// ---------------------------------------------------------------------------
// SMEM layout (dynamic, 192 KB):
//   A hi/lo: 128 rows x 512 B (XOR-swizzled 16B chunks) = 64 KB each
//   B double buffers: 2 x (hi 16 KB + lo 16 KB); rows = n (128), 128 B/row
// ---------------------------------------------------------------------------
#define OFF_AH   0
#define OFF_AL   65536
#define OFF_B    131072
#define SMEM_TOT 196608

// ---------------------------------------------------------------------------
__global__ void k_zero() {
  const size_t n4 = ((size_t)NUP * BB * COUT) / 4;
  const float4 z = make_float4(0.f, 0.f, 0.f, 0.f);
  const size_t stride = (size_t)gridDim.x * blockDim.x;
  for (size_t i = (size_t)blockIdx.x * blockDim.x + threadIdx.x; i < n4; i += stride)
    reinterpret_cast<float4*>(g_accum)[i] = z;
  for (size_t i = (size_t)blockIdx.x * blockDim.x + threadIdx.x; i < (size_t)NUP; i += stride)
    g_cnt[i] = 0;
}

__global__ void k_count(const int* __restrict__ neigh) {
  const int i = blockIdx.x * blockDim.x + threadIdx.x;
  if (i < VK) atomicAdd(&g_cnt[neigh[i]], 1);
}

// ---------------------------------------------------------------------------
// Prep: x [B][CIN][NLOW] f32 -> A_hi/A_lo [m = v*16+b][c] bf16 (hi/lo split)
// ---------------------------------------------------------------------------
__global__ void __launch_bounds__(256) prep_x(const float* __restrict__ x) {
  __shared__ float s[32][65];
  const int v0 = blockIdx.x * 64, c0 = blockIdx.y * 32, b = blockIdx.z;
  const int tid = threadIdx.x;
  for (int i = tid; i < 32 * 64; i += 256) {
    const int cl = i >> 6, vl = i & 63, v = v0 + vl;
    s[cl][vl] = (v < NLOW) ? x[((size_t)b * CIN + c0 + cl) * NLOW + v] : 0.f;
  }
  __syncthreads();
  for (int i = tid; i < 64 * 32; i += 256) {
    const int vl = i >> 5, cl = i & 31, v = v0 + vl;
    if (v < NLOW) {
      const float val = s[cl][vl];
      const __nv_bfloat16 hi = __float2bfloat16(val);
      const __nv_bfloat16 lo = __float2bfloat16(val - __bfloat162float(hi));
      const size_t m = (size_t)v * BB + b;
      g_Ah[m * CIN + c0 + cl] = hi;
      g_Al[m * CIN + c0 + cl] = lo;
    }
  }
}

// ---------------------------------------------------------------------------
// Prep: W [CIN][FF] f32 -> B_hi/B_lo [f][c] bf16 (transposed, hi/lo split)
// ---------------------------------------------------------------------------
__global__ void __launch_bounds__(256) prep_w(const float* __restrict__ w) {
  __shared__ float s[32][33];
  const int f0 = blockIdx.x * 32, c0 = blockIdx.y * 32;
  const int lane = threadIdx.x & 31, wr = threadIdx.x >> 5;
  for (int r = wr; r < 32; r += 8)
    s[r][lane] = w[(size_t)(c0 + r) * FF + f0 + lane];
  __syncthreads();
  for (int r = wr; r < 32; r += 8) {
    const float val = s[lane][r];
    const __nv_bfloat16 hi = __float2bfloat16(val);
    const __nv_bfloat16 lo = __float2bfloat16(val - __bfloat162float(hi));
    g_Bh[(size_t)(f0 + r) * CIN + c0 + lane] = hi;
    g_Bl[(size_t)(f0 + r) * CIN + c0 + lane] = lo;
  }
}

// ---------------------------------------------------------------------------
// Main kernel: warp-level bf16 mma.sync (hi/lo compensated) + atomic scatter.
// CTA = one 128-row m-tile, 256 threads = 8 warps (4m x 2n). A resident in
// smem; B streamed as 28 double-buffered 64-k-col sub-chunks (prefetch
// crosses k boundaries, so the epilogue overlaps the next k's B load).
// Epilogue: shfl-pair lanes -> red.global.add.v4.f32 into g_accum[u][b][co].
// ---------------------------------------------------------------------------
__global__ void __launch_bounds__(256, 1) k_mma(const float* __restrict__ bias,
                                                const int* __restrict__ neigh) {
  extern __shared__ __align__(128) char smem[];
  const uint32_t base = smem_u32(smem);
  const int tid  = threadIdx.x;
  const int wid  = tid >> 5;
  const int lane = tid & 31;
  const int wm   = wid & 3;        // warp m-row (0..3) -> 32 rows
  const int wn   = wid >> 2;       // warp n-col (0..1) -> 64 cols
  const int m0w  = wm * 32;
  const int n0w  = wn * 64;
  const int m0   = blockIdx.x * 128;

  // ---- A tile (hi + lo) resident: one cp.async group ----
  for (int i = tid; i < 4096; i += 256) {
    const int r = i >> 5, cc = i & 31;
    const uint32_t dst = (uint32_t)(r * 512 + ((cc ^ (r & 7)) << 4));
    const size_t src = ((size_t)(m0 + r)) * CIN + cc * 8;
    cpa16(base + OFF_AH + dst, &g_Ah[src]);
    cpa16(base + OFF_AL + dst, &g_Al[src]);
  }
  cpa_commit();

  // B sub-chunk loader: s = k*4 + ch (64 k-cols), buffer = s&1
  auto loadB = [&](int s) {
    const int k = s >> 2, ch = s & 3;
    const uint32_t bh = base + OFF_B + (uint32_t)((s & 1) * 32768);
    const uint32_t bl = bh + 16384;
    for (int i = tid; i < 1024; i += 256) {
      const int n = i >> 3, cc = i & 7;
      const uint32_t dst = (uint32_t)(n * 128 + ((cc ^ (n & 7)) << 4));
      const size_t src = ((size_t)(k * COUT + n)) * CIN + ch * 64 + cc * 8;
      cpa16(bh + dst, &g_Bh[src]);
      cpa16(bl + dst, &g_Bl[src]);
    }
    cpa_commit();
  };

  loadB(0);

  // Per-lane ldmatrix address components (identical to the passing round-9)
  const int asub = lane >> 3;
  const int arow_lo = (asub & 1) * 8 + (lane & 7);
  const int achunk_add = asub >> 1;
  const int bsub = (lane >> 3) & 1;
  const int brow = lane & 7;

  float d[2][8][4];

  for (int s = 0; s < NSUB; ++s) {
    if (s + 1 < NSUB) { loadB(s + 1); cpa_wait1(); }
    else              { cpa_wait0(); }
    __syncthreads();

    if ((s & 3) == 0) {
#pragma unroll
      for (int mt = 0; mt < 2; ++mt)
#pragma unroll
        for (int nt = 0; nt < 8; ++nt)
#pragma unroll
          for (int q = 0; q < 4; ++q) d[mt][nt][q] = 0.f;
    }

    const int ch = s & 3;
    const uint32_t bhB = base + OFF_B + (uint32_t)((s & 1) * 32768);
    const uint32_t blB = bhB + 16384;

#pragma unroll
    for (int ks = 0; ks < 4; ++ks) {          // 4 x k16 within 64 k-cols
      const int cA = ch * 8 + ks * 2 + achunk_add;
      uint32_t ah[2][4], al[2][4];
#pragma unroll
      for (int mt = 0; mt < 2; ++mt) {
        const int row = m0w + mt * 16 + arow_lo;
        const uint32_t aoff = (uint32_t)(row * 512 + ((cA ^ (row & 7)) << 4));
        ldsm_x4(ah[mt], base + OFF_AH + aoff);
        ldsm_x4(al[mt], base + OFF_AL + aoff);
      }
      const int cB = ks * 2 + bsub;
      const uint32_t boff0 =
          (uint32_t)((n0w + brow) * 128 + ((cB ^ brow) << 4));
#pragma unroll
      for (int nt = 0; nt < 8; ++nt) {
        uint32_t bh0, bh1, bl0, bl1;
        const uint32_t ba = boff0 + (uint32_t)(nt * 1024);
        ldsm_x2(bh0, bh1, bhB + ba);
        ldsm_x2(bl0, bl1, blB + ba);
#pragma unroll
        for (int mt = 0; mt < 2; ++mt) {
          mma16816(d[mt][nt], ah[mt], bh0, bh1);   // hi*hi
          mma16816(d[mt][nt], ah[mt], bl0, bl1);   // hi*lo
          mma16816(d[mt][nt], al[mt], bh0, bh1);   // lo*hi
        }
      }
    }
    __syncthreads();   // compute(s) done before next iter overwrites buffer

    // ---- Epilogue when k's last sub-chunk is done (overlaps next B load) ----
    if ((s & 3) == 3) {
      const int k = s >> 2;
      const int l4 = lane >> 2;            // row-in-8
      const int l2 = (lane & 3) * 2;       // own col pair
      const int cb4 = (lane & 2) * 2;      // v4 col base (even pairs)
#pragma unroll
      for (int mt = 0; mt < 2; ++mt) {
#pragma unroll
        for (int h = 0; h < 2; ++h) {
          const int m = m0 + m0w + mt * 16 + h * 8 + l4;
          const bool valid = (m < MTOT);
          const int v = m >> 4;
          const int b = m & 15;
          const int u = valid ? neigh[v * KK + k] : 0;
          float* dp = g_accum + ((size_t)u * BB + b) * COUT;
#pragma unroll
          for (int nt = 0; nt < 8; ++nt) {
            const int col = n0w + nt * 8 + l2;
            const float2 bb =
                *reinterpret_cast<const float2*>(&bias[k * COUT + col]);
            float v0 = d[mt][nt][h * 2 + 0] + bb.x;
            float v1 = d[mt][nt][h * 2 + 1] + bb.y;
            const float p0 = __shfl_xor_sync(0xFFFFFFFFu, v0, 1);
            const float p1 = __shfl_xor_sync(0xFFFFFFFFu, v1, 1);
            if (valid && ((lane & 1) == 0))
              red4g(dp + n0w + nt * 8 + cb4, v0, v1, p0, p1);
          }
        }
      }
    }
  }
}

// ---------------------------------------------------------------------------
// Finalize: divide by counts and transpose [u][bc] -> out[bc][u].
// ---------------------------------------------------------------------------
__global__ void __launch_bounds__(256) k_finalize(float* __restrict__ out) {
  __shared__ float t[32][129];
  __shared__ float inv[32];
  const int u0 = blockIdx.x * 32, c0 = blockIdx.y * 128;
  const int tid = threadIdx.x, lane = tid & 31, wr = tid >> 5;

  if (tid < 32) inv[tid] = (u0 + tid < NUP) ? 1.0f / (float)g_cnt[u0 + tid] : 0.f;

  for (int i = tid; i < 1024; i += 256) {   // 32 u x 32 float4
    const int ur = i >> 5, c4 = i & 31;
    const int u = u0 + ur;
    float4 v = make_float4(0.f, 0.f, 0.f, 0.f);
    if (u < NUP)
      v = *reinterpret_cast<const float4*>(&g_accum[(size_t)u * (BB * COUT) + c0 + c4 * 4]);
    t[ur][c4 * 4 + 0] = v.x;
    t[ur][c4 * 4 + 1] = v.y;
    t[ur][c4 * 4 + 2] = v.z;
    t[ur][c4 * 4 + 3] = v.w;
  }
  __syncthreads();

  const int u = u0 + lane;
  if (u < NUP) {
    const float iv = inv[lane];
    for (int r = wr; r < 128; r += 8)
      out[(size_t)(c0 + r) * NUP + u] = t[lane][r] * iv;
  }
}

// ---------------------------------------------------------------------------
// Launch. Order puts k_mma at position 4 — the slot ncu captured last round.
// (k_count feeds only k_finalize, so it can run after k_mma.)
// ---------------------------------------------------------------------------
extern "C" void kernel_launch(void* const* d_in, const int* in_sizes, int n_in,
                              void* d_out, int out_size) {
  const float* x     = (const float*)d_in[0];
  const float* w     = (const float*)d_in[1];
  const float* bias  = (const float*)d_in[2];
  const int*   neigh = (const int*)d_in[3];
  float* out = (float*)d_out;

  k_zero<<<2048, 256>>>();                                     // 1
  prep_x<<<dim3((NLOW + 63) / 64, CIN / 32, BB), 256>>>(x);    // 2
  prep_w<<<dim3(FF / 32, CIN / 32), 256>>>(w);                 // 3

  cudaFuncSetAttribute(k_mma, cudaFuncAttributeMaxDynamicSharedMemorySize, SMEM_TOT);
  k_mma<<<MTILES, 256, SMEM_TOT>>>(bias, neigh);               // 4

  k_count<<<(VK + 255) / 256, 256>>>(neigh);                   // 5
  k_finalize<<<dim3((NUP + 31) / 32, (BB * COUT) / 128), 256>>>(out);  // 6
}